// round 8
// baseline (speedup 1.0000x reference)
#include <cuda_runtime.h>

#define B_ 256
#define T_ 1024
#define K_ 128
#define LN2 0.69314718055994531f

__device__ float g_logz[B_];
__device__ float g_gold[B_];

__device__ __forceinline__ void fma2(unsigned long long &acc, unsigned long long a, unsigned long long b) {
    asm("fma.rn.f32x2 %0, %1, %2, %0;" : "+l"(acc) : "l"(a), "l"(b));
}
__device__ __forceinline__ unsigned long long add2(unsigned long long a, unsigned long long b) {
    unsigned long long c;
    asm("add.rn.f32x2 %0, %1, %2;" : "=l"(c) : "l"(a), "l"(b));
    return c;
}
__device__ __forceinline__ unsigned long long pack2(float x, float y) {
    unsigned long long r;
    asm("mov.b64 %0, {%1, %2};" : "=l"(r) : "f"(x), "f"(y));
    return r;
}
__device__ __forceinline__ float2 unpack2(unsigned long long v) {
    float2 f;
    asm("mov.b64 {%0, %1}, %2;" : "=f"(f.x), "=f"(f.y) : "l"(v));
    return f;
}
__device__ __forceinline__ float warp_sum(float v) {
    #pragma unroll
    for (int o = 16; o > 0; o >>= 1) v += __shfl_xor_sync(0xffffffffu, v, o);
    return v;
}
__device__ __forceinline__ int imin(int a, int b) { return a < b ? a : b; }

// Forward logZ, exp domain: p_t = (p_{t-1} @ E) * exp(em_t) * 2^-ke, masked.
// ke = exponent(p_prev[0]) peeked from the first GEMV load (CTA-uniform, free).
// One batch per CTA of 128 threads; thread j owns state j; E column in regs.
// One __syncthreads per step; ALL prefetch sits between STS and the barrier
// (executes in the barrier's STS-drain window). 4-step unroll: int4 mask load
// once per 4 steps, emissions double-buffered 4-wide, one MUFU exp per step.
__global__ __launch_bounds__(128, 2) void crf_fwd(
    const float* __restrict__ emis,   // (B,T,K)
    const int* __restrict__ mask,     // (B,T) int32
    const float* __restrict__ start,  // (K)
    const float* __restrict__ endv,   // (K)
    const float* __restrict__ trans)  // (K,K)
{
    const int b = blockIdx.x;
    const int j = threadIdx.x;
    __shared__ __align__(16) float pb0[K_];
    __shared__ __align__(16) float pb1[K_];
    __shared__ float wred[4];

    // E[:,j] packed over i-pairs
    unsigned long long e2[K_ / 2];
    #pragma unroll
    for (int k = 0; k < K_ / 2; ++k) {
        float ea  = __expf(trans[(2 * k) * K_ + j]);
        float ebv = __expf(trans[(2 * k + 1) * K_ + j]);
        e2[k] = pack2(ea, ebv);
    }

    const float* __restrict__ eb = emis + (size_t)b * T_ * K_;
    const int* __restrict__ mb = mask + (size_t)b * T_;

    float p = __expf(start[j] + eb[j]);  // t = 0
    int kacc = 0;
    pb0[j] = p;

    // prologue data: steps 1..3 scalar; iter pipeline primed for t=4..11
    float pe1 = __expf(eb[1 * K_ + j]);
    float pe2 = __expf(eb[2 * K_ + j]);
    float pe3 = __expf(eb[3 * K_ + j]);
    int pm1 = mb[1], pm2 = mb[2], pm3 = mb[3];

    float eem0 = __expf(eb[4 * K_ + j]);
    float eem1 = __expf(eb[5 * K_ + j]);
    float eem2 = __expf(eb[6 * K_ + j]);
    float eem3 = __expf(eb[7 * K_ + j]);
    float rA0 = eb[8 * K_ + j], rA1 = eb[9 * K_ + j];
    float rA2 = eb[10 * K_ + j], rA3 = eb[11 * K_ + j];
    int4 mk4 = *(const int4*)(mb + 4);
    __syncthreads();

#define CRF_STEP(PRD, PWR, EEM, MK, POST)                                     \
    {                                                                         \
        const ulonglong2* __restrict__ pv = (const ulonglong2*)(PRD);         \
        ulonglong2 q0 = pv[0];                                                \
        float2 f0 = unpack2(q0.x);                                            \
        unsigned int xb = __float_as_uint(f0.x) >> 23;                        \
        int ke = (int)xb - 127;                                               \
        float scale = __uint_as_float((254u - xb) << 23);  /* 2^-ke exact */  \
        int mk_ = (MK);                                                       \
        if (!mk_) { ke = 0; scale = 1.0f; }                                   \
        float eemx = (EEM) * scale;                                           \
        kacc += ke;                                                           \
        unsigned long long a0 = 0ull, a1 = 0ull, a2 = 0ull, a3 = 0ull;        \
        unsigned long long a4 = 0ull, a5 = 0ull, a6 = 0ull, a7 = 0ull;        \
        ulonglong2 q1 = pv[1];                                                \
        ulonglong2 q2 = pv[2];                                                \
        ulonglong2 q3 = pv[3];                                                \
        fma2(a0, q0.x, e2[0]); fma2(a1, q0.y, e2[1]);                         \
        fma2(a2, q1.x, e2[2]); fma2(a3, q1.y, e2[3]);                         \
        fma2(a4, q2.x, e2[4]); fma2(a5, q2.y, e2[5]);                         \
        fma2(a6, q3.x, e2[6]); fma2(a7, q3.y, e2[7]);                         \
        _Pragma("unroll")                                                     \
        for (int k = 1; k < 8; ++k) {                                         \
            ulonglong2 r0 = pv[4 * k];                                        \
            ulonglong2 r1 = pv[4 * k + 1];                                    \
            ulonglong2 r2 = pv[4 * k + 2];                                    \
            ulonglong2 r3 = pv[4 * k + 3];                                    \
            fma2(a0, r0.x, e2[8 * k]);     fma2(a1, r0.y, e2[8 * k + 1]);     \
            fma2(a2, r1.x, e2[8 * k + 2]); fma2(a3, r1.y, e2[8 * k + 3]);     \
            fma2(a4, r2.x, e2[8 * k + 4]); fma2(a5, r2.y, e2[8 * k + 5]);     \
            fma2(a6, r3.x, e2[8 * k + 6]); fma2(a7, r3.y, e2[8 * k + 7]);     \
        }                                                                     \
        a0 = add2(a0, a1); a2 = add2(a2, a3);                                 \
        a4 = add2(a4, a5); a6 = add2(a6, a7);                                 \
        a0 = add2(a0, a2); a4 = add2(a4, a6);                                 \
        a0 = add2(a0, a4);                                                    \
        float2 sp = unpack2(a0);                                              \
        float s = sp.x + sp.y;                                                \
        p = mk_ ? s * eemx : p;                                               \
        (PWR)[j] = p;                                                         \
        POST                                                                  \
        __syncthreads();                                                      \
    }

    // prologue steps 1..3 (parity: t reads (t+1)&1, writes t&1)
    CRF_STEP(pb0, pb1, pe1, pm1, {})
    CRF_STEP(pb1, pb0, pe2, pm2, {})
    CRF_STEP(pb0, pb1, pe3, pm3, {})

    // main: t = 4, 8, ..., 1020 (255 iterations of 4 steps)
    float rB0, rB1, rB2, rB3, x0, x1, x2, x3;
    int4 mk4n;
    for (int t = 4; t < T_; t += 4) {
        // step a (t): rd pb1, wr pb0; prefetch next raws + mask block
        CRF_STEP(pb1, pb0, eem0, mk4.x, {
            rB0 = eb[(size_t)imin(t + 8, T_ - 1) * K_ + j];
            rB1 = eb[(size_t)imin(t + 9, T_ - 1) * K_ + j];
            rB2 = eb[(size_t)imin(t + 10, T_ - 1) * K_ + j];
            rB3 = eb[(size_t)imin(t + 11, T_ - 1) * K_ + j];
            mk4n = *(const int4*)(mb + imin(t + 4, T_ - 4));
        })
        // steps b..d: one/two exps of the raws loaded LAST iteration
        CRF_STEP(pb0, pb1, eem1, mk4.y, { x0 = __expf(rA0); })
        CRF_STEP(pb1, pb0, eem2, mk4.z, { x1 = __expf(rA1); })
        CRF_STEP(pb0, pb1, eem3, mk4.w, { x2 = __expf(rA2); x3 = __expf(rA3); })
        eem0 = x0; eem1 = x1; eem2 = x2; eem3 = x3;
        rA0 = rB0; rA1 = rB1; rA2 = rB2; rA3 = rB3;
        mk4 = mk4n;
    }
#undef CRF_STEP

    // final write lives in pb1 (t=1023 wrote pb1); p register is current
    // logZ = ln2*kacc + log(sum_j p_j * exp(end_j))
    float v = p * __expf(endv[j]);
    float ws = warp_sum(v);
    if ((j & 31) == 0) wred[j >> 5] = ws;
    __syncthreads();
    if (j == 0) {
        float sm = (wred[0] + wred[1]) + (wred[2] + wred[3]);
        g_logz[b] = LN2 * (float)kacc + __logf(sm);
    }
}

// Gold path score: one batch per CTA of 128 threads, strided over t.
__global__ void crf_gold(
    const float* __restrict__ emis,
    const int* __restrict__ tags,
    const int* __restrict__ mask,
    const float* __restrict__ start,
    const float* __restrict__ endv,
    const float* __restrict__ trans)
{
    const int b = blockIdx.x;
    const int tid = threadIdx.x;
    const float* __restrict__ eb = emis + (size_t)b * T_ * K_;
    const int* __restrict__ tg = tags + (size_t)b * T_;
    const int* __restrict__ mb = mask + (size_t)b * T_;

    float sc = 0.0f;
    int cnt = 0;
    for (int t = tid; t < T_; t += 128) {
        int mt = mb[t];
        cnt += mt ? 1 : 0;
        if (t >= 1 && mt && mb[t - 1]) {
            int pr = tg[t - 1]; pr = pr < 0 ? 0 : pr;
            int cr = tg[t];     cr = cr < 0 ? 0 : cr;
            sc += trans[pr * K_ + cr] + eb[(size_t)t * K_ + cr];
        }
    }

    __shared__ float wsc[4];
    __shared__ int wcn[4];
    float s = warp_sum(sc);
    int c = cnt;
    #pragma unroll
    for (int o = 16; o > 0; o >>= 1) c += __shfl_xor_sync(0xffffffffu, c, o);
    if ((tid & 31) == 0) { wsc[tid >> 5] = s; wcn[tid >> 5] = c; }
    __syncthreads();
    if (tid == 0) {
        float total = (wsc[0] + wsc[1]) + (wsc[2] + wsc[3]);
        int ctot = wcn[0] + wcn[1] + wcn[2] + wcn[3];
        int t0 = tg[0];
        float sc0 = (start[t0] + eb[t0]) * (mb[0] ? 1.0f : 0.0f);
        int lenm1 = ctot - 1;
        int last = tg[lenm1];
        g_gold[b] = total + sc0 + endv[last];
    }
}

// Final: mean over batches of (logZ - gold), fixed-order tree reduction.
__global__ void crf_finish(float* __restrict__ out) {
    __shared__ float sm[B_];
    int i = threadIdx.x;
    sm[i] = g_logz[i] - g_gold[i];
    __syncthreads();
    #pragma unroll
    for (int s = 128; s > 0; s >>= 1) {
        if (i < s) sm[i] += sm[i + s];
        __syncthreads();
    }
    if (i == 0) out[0] = sm[0] * (1.0f / B_);
}

extern "C" void kernel_launch(void* const* d_in, const int* in_sizes, int n_in,
                              void* d_out, int out_size) {
    const float* emis   = (const float*)d_in[0];
    const int* tags     = (const int*)d_in[1];
    const int* mask     = (const int*)d_in[2];
    const float* start  = (const float*)d_in[3];
    const float* endv   = (const float*)d_in[4];
    const float* trans  = (const float*)d_in[5];
    float* out = (float*)d_out;

    crf_fwd<<<B_, K_>>>(emis, mask, start, endv, trans);
    crf_gold<<<B_, K_>>>(emis, tags, mask, start, endv, trans);
    crf_finish<<<1, B_>>>(out);
}

// round 9
// speedup vs baseline: 1.1020x; 1.1020x over previous
#include <cuda_runtime.h>

#define B_ 256
#define T_ 1024
#define K_ 128
#define LN2 0.69314718055994531f

__device__ float g_logz[B_];
__device__ float g_gold[B_];

__device__ __forceinline__ void fma2(unsigned long long &acc, unsigned long long a, unsigned long long b) {
    asm("fma.rn.f32x2 %0, %1, %2, %0;" : "+l"(acc) : "l"(a), "l"(b));
}
__device__ __forceinline__ unsigned long long add2(unsigned long long a, unsigned long long b) {
    unsigned long long c;
    asm("add.rn.f32x2 %0, %1, %2;" : "=l"(c) : "l"(a), "l"(b));
    return c;
}
__device__ __forceinline__ unsigned long long pack2(float x, float y) {
    unsigned long long r;
    asm("mov.b64 %0, {%1, %2};" : "=l"(r) : "f"(x), "f"(y));
    return r;
}
__device__ __forceinline__ float2 unpack2(unsigned long long v) {
    float2 f;
    asm("mov.b64 {%0, %1}, %2;" : "=f"(f.x), "=f"(f.y) : "l"(v));
    return f;
}
__device__ __forceinline__ float warp_sum(float v) {
    #pragma unroll
    for (int o = 16; o > 0; o >>= 1) v += __shfl_xor_sync(0xffffffffu, v, o);
    return v;
}

// Forward logZ, exp domain: p_t = (p_{t-1} @ E) * exp(em_t) * 2^-ke, masked,
// where ke = exponent(p_{t-1}[0]) -- read for free from the first GEMV LDS.
// One batch per CTA of 128 threads; thread j owns state j; E column in regs.
// Exactly ONE __syncthreads per step; no warp reductions in the loop.
// NEW vs R6: odd-blockIdx CTAs start ~350 cycles late (dependent-FADD delay)
// so the two co-resident CTAs on an SM run anti-phased: one CTA's FMA burst
// overlaps the other's LDS-head/tree-tail/barrier segment.
__global__ __launch_bounds__(128, 2) void crf_fwd(
    const float* __restrict__ emis,   // (B,T,K)
    const int* __restrict__ mask,     // (B,T) int32
    const float* __restrict__ start,  // (K)
    const float* __restrict__ endv,   // (K)
    const float* __restrict__ trans)  // (K,K)
{
    const int b = blockIdx.x;
    const int j = threadIdx.x;
    __shared__ __align__(16) float pb0[K_];
    __shared__ __align__(16) float pb1[K_];
    __shared__ float wred[4];

    // E[:,j] packed over i-pairs
    unsigned long long e2[K_ / 2];
    #pragma unroll
    for (int k = 0; k < K_ / 2; ++k) {
        float ea  = __expf(trans[(2 * k) * K_ + j]);
        float ebv = __expf(trans[(2 * k + 1) * K_ + j]);
        e2[k] = pack2(ea, ebv);
    }

    const float* __restrict__ eb = emis + (size_t)b * T_ * K_;
    const int* __restrict__ mb = mask + (size_t)b * T_;

    float p = __expf(start[j] + eb[j]);  // t = 0
    int kacc = 0;
    pb0[j] = p;

    // 3-deep prefetch of exp(em) and mask
    float eA = __expf(eb[1 * K_ + j]);
    float eB = __expf(eb[2 * K_ + j]);
    float eC = __expf(eb[3 * K_ + j]);
    int mA = mb[1], mB = mb[2], mC = mb[3];

    // anti-phase stagger: odd CTAs burn ~350 cycles once (88 dependent FADDs)
    if (b & 1) {
        float x = p;
        #pragma unroll
        for (int d = 0; d < 88; ++d)
            asm volatile("add.f32 %0, %0, 0f3F800000;" : "+f"(x));
        if (__float_as_uint(x) == 0xDEADBEEFu) pb1[j] = x;  // never true
    }
    __syncthreads();

#define CRF_STEP(T_IDX, PRD, PWR)                                             \
    {                                                                         \
        const int t_ = (T_IDX);                                               \
        float eem = eA; eA = eB; eB = eC;                                     \
        int mk = mA; mA = mB; mB = mC;                                        \
        if (t_ + 3 < T_) {                                                    \
            eC = __expf(eb[(size_t)(t_ + 3) * K_ + j]);                       \
            mC = mb[t_ + 3];                                                  \
        }                                                                     \
        const ulonglong2* __restrict__ pv = (const ulonglong2*)(PRD);         \
        ulonglong2 q0 = pv[0];                                                \
        float2 f0 = unpack2(q0.x);                                            \
        unsigned int xb = __float_as_uint(f0.x) >> 23;                        \
        int ke = (int)xb - 127;                                               \
        float scale = __uint_as_float((254u - xb) << 23);  /* 2^-ke exact */  \
        if (!mk) { ke = 0; scale = 1.0f; }                                    \
        float eemx = eem * scale;                                             \
        kacc += ke;                                                           \
        unsigned long long a0 = 0ull, a1 = 0ull, a2 = 0ull, a3 = 0ull;        \
        unsigned long long a4 = 0ull, a5 = 0ull, a6 = 0ull, a7 = 0ull;        \
        ulonglong2 q1 = pv[1];                                                \
        ulonglong2 q2 = pv[2];                                                \
        ulonglong2 q3 = pv[3];                                                \
        fma2(a0, q0.x, e2[0]); fma2(a1, q0.y, e2[1]);                         \
        fma2(a2, q1.x, e2[2]); fma2(a3, q1.y, e2[3]);                         \
        fma2(a4, q2.x, e2[4]); fma2(a5, q2.y, e2[5]);                         \
        fma2(a6, q3.x, e2[6]); fma2(a7, q3.y, e2[7]);                         \
        _Pragma("unroll")                                                     \
        for (int k = 1; k < 8; ++k) {                                         \
            ulonglong2 r0 = pv[4 * k];                                        \
            ulonglong2 r1 = pv[4 * k + 1];                                    \
            ulonglong2 r2 = pv[4 * k + 2];                                    \
            ulonglong2 r3 = pv[4 * k + 3];                                    \
            fma2(a0, r0.x, e2[8 * k]);     fma2(a1, r0.y, e2[8 * k + 1]);     \
            fma2(a2, r1.x, e2[8 * k + 2]); fma2(a3, r1.y, e2[8 * k + 3]);     \
            fma2(a4, r2.x, e2[8 * k + 4]); fma2(a5, r2.y, e2[8 * k + 5]);     \
            fma2(a6, r3.x, e2[8 * k + 6]); fma2(a7, r3.y, e2[8 * k + 7]);     \
        }                                                                     \
        a0 = add2(a0, a1); a2 = add2(a2, a3);                                 \
        a4 = add2(a4, a5); a6 = add2(a6, a7);                                 \
        a0 = add2(a0, a2); a4 = add2(a4, a6);                                 \
        a0 = add2(a0, a4);                                                    \
        float2 sp = unpack2(a0);                                              \
        float s = sp.x + sp.y;                                                \
        p = mk ? s * eemx : p;                                                \
        (PWR)[j] = p;                                                         \
        __syncthreads();                                                      \
    }

    // 1023 steps: 511 unrolled pairs + 1 tail
    for (int t = 1; t < T_ - 1; t += 2) {
        CRF_STEP(t,     pb0, pb1)
        CRF_STEP(t + 1, pb1, pb0)
    }
    CRF_STEP(T_ - 1, pb0, pb1)
#undef CRF_STEP

    // logZ = ln2*kacc + log(sum_j p_j * exp(end_j))
    float v = p * __expf(endv[j]);
    float ws = warp_sum(v);
    if ((j & 31) == 0) wred[j >> 5] = ws;
    __syncthreads();
    if (j == 0) {
        float sm = (wred[0] + wred[1]) + (wred[2] + wred[3]);
        g_logz[b] = LN2 * (float)kacc + __logf(sm);
    }
}

// Gold path score: one batch per CTA of 128 threads, strided over t.
__global__ void crf_gold(
    const float* __restrict__ emis,
    const int* __restrict__ tags,
    const int* __restrict__ mask,
    const float* __restrict__ start,
    const float* __restrict__ endv,
    const float* __restrict__ trans)
{
    const int b = blockIdx.x;
    const int tid = threadIdx.x;
    const float* __restrict__ eb = emis + (size_t)b * T_ * K_;
    const int* __restrict__ tg = tags + (size_t)b * T_;
    const int* __restrict__ mb = mask + (size_t)b * T_;

    float sc = 0.0f;
    int cnt = 0;
    for (int t = tid; t < T_; t += 128) {
        int mt = mb[t];
        cnt += mt ? 1 : 0;
        if (t >= 1 && mt && mb[t - 1]) {
            int pr = tg[t - 1]; pr = pr < 0 ? 0 : pr;
            int cr = tg[t];     cr = cr < 0 ? 0 : cr;
            sc += trans[pr * K_ + cr] + eb[(size_t)t * K_ + cr];
        }
    }

    __shared__ float wsc[4];
    __shared__ int wcn[4];
    float s = warp_sum(sc);
    int c = cnt;
    #pragma unroll
    for (int o = 16; o > 0; o >>= 1) c += __shfl_xor_sync(0xffffffffu, c, o);
    if ((tid & 31) == 0) { wsc[tid >> 5] = s; wcn[tid >> 5] = c; }
    __syncthreads();
    if (tid == 0) {
        float total = (wsc[0] + wsc[1]) + (wsc[2] + wsc[3]);
        int ctot = wcn[0] + wcn[1] + wcn[2] + wcn[3];
        int t0 = tg[0];
        float sc0 = (start[t0] + eb[t0]) * (mb[0] ? 1.0f : 0.0f);
        int lenm1 = ctot - 1;
        int last = tg[lenm1];
        g_gold[b] = total + sc0 + endv[last];
    }
}

// Final: mean over batches of (logZ - gold), fixed-order tree reduction.
__global__ void crf_finish(float* __restrict__ out) {
    __shared__ float sm[B_];
    int i = threadIdx.x;
    sm[i] = g_logz[i] - g_gold[i];
    __syncthreads();
    #pragma unroll
    for (int s = 128; s > 0; s >>= 1) {
        if (i < s) sm[i] += sm[i + s];
        __syncthreads();
    }
    if (i == 0) out[0] = sm[0] * (1.0f / B_);
}

extern "C" void kernel_launch(void* const* d_in, const int* in_sizes, int n_in,
                              void* d_out, int out_size) {
    const float* emis   = (const float*)d_in[0];
    const int* tags     = (const int*)d_in[1];
    const int* mask     = (const int*)d_in[2];
    const float* start  = (const float*)d_in[3];
    const float* endv   = (const float*)d_in[4];
    const float* trans  = (const float*)d_in[5];
    float* out = (float*)d_out;

    crf_fwd<<<B_, K_>>>(emis, mask, start, endv, trans);
    crf_gold<<<B_, K_>>>(emis, tags, mask, start, endv, trans);
    crf_finish<<<1, B_>>>(out);
}